// round 1
// baseline (speedup 1.0000x reference)
#include <cuda_runtime.h>
#include <cuda_bf16.h>

#define T_LEN 16384
#define HID   512
#define NCHUNK 128
#define CHUNK_L (T_LEN / NCHUNK)   // 128

// Scratch (device globals -> no runtime allocation)
__device__ float g_a[T_LEN * HID];     // a_t = 1 - z_t
__device__ float g_b[T_LEN * HID];     // b_t = z_t * hcand_t
__device__ float g_s[T_LEN * HID];     // scanned hidden states
__device__ float g_aggA[NCHUNK * HID];
__device__ float g_aggB[NCHUNK * HID];
__device__ float g_pref[NCHUNK * HID]; // state entering each chunk

// ---------------------------------------------------------------------------
// GEMM1: computes Z = X*Wz^T + bz and Hc = X*Wh^T + bh for the same C tile,
// sharing the X smem tile, then writes a = 1-sigmoid(Z), b = sigmoid(Z)*Hc.
// Tile: BM=128, BN=64, BK=32. 256 threads, 8x4 microtile, two accumulators.
// ---------------------------------------------------------------------------
__global__ __launch_bounds__(256) void gemm_zh_kernel(
    const float* __restrict__ X,
    const float* __restrict__ Wz, const float* __restrict__ bz,
    const float* __restrict__ Wh, const float* __restrict__ bh)
{
    __shared__ float Xs[32][128];
    __shared__ float Zs[32][64];
    __shared__ float Hs[32][64];

    const int tid = threadIdx.x;
    const int m0 = blockIdx.y * 128;
    const int n0 = blockIdx.x * 64;

    // loader mapping
    const int xr  = tid & 127;          // X row within tile
    const int xc4 = (tid >> 7) * 4;     // 4 float4s along K
    const int wr  = tid & 63;           // W row within tile
    const int wc4 = (tid >> 6) * 2;     // 2 float4s along K

    // compute mapping
    const int tx = tid & 15;            // n direction (16 * 4 = 64)
    const int ty = tid >> 4;            // m direction (16 * 8 = 128)

    float accz[8][4];
    float acch[8][4];
    #pragma unroll
    for (int i = 0; i < 8; i++)
        #pragma unroll
        for (int j = 0; j < 4; j++) { accz[i][j] = 0.f; acch[i][j] = 0.f; }

    for (int k0 = 0; k0 < 512; k0 += 32) {
        // load X tile (transposed into Xs[k][m])
        #pragma unroll
        for (int j = 0; j < 4; j++) {
            const int kk = (xc4 + j) * 4;
            float4 v = *(const float4*)(X + (size_t)(m0 + xr) * 512 + k0 + kk);
            Xs[kk + 0][xr] = v.x; Xs[kk + 1][xr] = v.y;
            Xs[kk + 2][xr] = v.z; Xs[kk + 3][xr] = v.w;
        }
        // load Wz / Wh tiles (transposed into Ws[k][n])
        #pragma unroll
        for (int j = 0; j < 2; j++) {
            const int kk = (wc4 + j) * 4;
            float4 vz = *(const float4*)(Wz + (size_t)(n0 + wr) * 512 + k0 + kk);
            Zs[kk + 0][wr] = vz.x; Zs[kk + 1][wr] = vz.y;
            Zs[kk + 2][wr] = vz.z; Zs[kk + 3][wr] = vz.w;
            float4 vh = *(const float4*)(Wh + (size_t)(n0 + wr) * 512 + k0 + kk);
            Hs[kk + 0][wr] = vh.x; Hs[kk + 1][wr] = vh.y;
            Hs[kk + 2][wr] = vh.z; Hs[kk + 3][wr] = vh.w;
        }
        __syncthreads();

        #pragma unroll
        for (int k = 0; k < 32; k++) {
            float4 xa = *(const float4*)&Xs[k][ty * 8];
            float4 xb = *(const float4*)&Xs[k][ty * 8 + 4];
            float4 wz = *(const float4*)&Zs[k][tx * 4];
            float4 wh = *(const float4*)&Hs[k][tx * 4];
            float xm[8] = {xa.x, xa.y, xa.z, xa.w, xb.x, xb.y, xb.z, xb.w};
            float fz[4] = {wz.x, wz.y, wz.z, wz.w};
            float fh[4] = {wh.x, wh.y, wh.z, wh.w};
            #pragma unroll
            for (int i = 0; i < 8; i++)
                #pragma unroll
                for (int j = 0; j < 4; j++) {
                    accz[i][j] += xm[i] * fz[j];
                    acch[i][j] += xm[i] * fh[j];
                }
        }
        __syncthreads();
    }

    // epilogue: a = 1 - sigmoid(z), b = sigmoid(z) * hcand
    float bzv[4], bhv[4];
    #pragma unroll
    for (int j = 0; j < 4; j++) {
        bzv[j] = bz[n0 + tx * 4 + j];
        bhv[j] = bh[n0 + tx * 4 + j];
    }
    #pragma unroll
    for (int i = 0; i < 8; i++) {
        const int m = m0 + ty * 8 + i;
        float4 av, bv;
        float tmpa[4], tmpb[4];
        #pragma unroll
        for (int j = 0; j < 4; j++) {
            float z = 1.f / (1.f + __expf(-(accz[i][j] + bzv[j])));
            tmpa[j] = 1.f - z;
            tmpb[j] = z * (acch[i][j] + bhv[j]);
        }
        av.x = tmpa[0]; av.y = tmpa[1]; av.z = tmpa[2]; av.w = tmpa[3];
        bv.x = tmpb[0]; bv.y = tmpb[1]; bv.z = tmpb[2]; bv.w = tmpb[3];
        *(float4*)(g_a + (size_t)m * HID + n0 + tx * 4) = av;
        *(float4*)(g_b + (size_t)m * HID + n0 + tx * 4) = bv;
    }
}

// ---------------------------------------------------------------------------
// Scan phase 1: per-(chunk, channel) segment aggregate (A, B).
// grid = NCHUNK blocks, 512 threads (one per channel). Coalesced across h.
// ---------------------------------------------------------------------------
__global__ __launch_bounds__(512) void scan_phase1(void)
{
    const int c = blockIdx.x;
    const int h = threadIdx.x;
    float A = 1.f, B = 0.f;
    size_t base = ((size_t)c * CHUNK_L) * HID + h;
    #pragma unroll 4
    for (int t = 0; t < CHUNK_L; t++) {
        float a = g_a[base];
        float b = g_b[base];
        A = a * A;
        B = a * B + b;
        base += HID;
    }
    g_aggA[c * HID + h] = A;
    g_aggB[c * HID + h] = B;
}

// ---------------------------------------------------------------------------
// Scan phase 2: sequential scan over chunk aggregates per channel.
// 1 block, 512 threads. Writes the state entering each chunk.
// ---------------------------------------------------------------------------
__global__ __launch_bounds__(512) void scan_phase2(void)
{
    const int h = threadIdx.x;
    float s = 0.f;  // h_0 = 0
    for (int c = 0; c < NCHUNK; c++) {
        g_pref[c * HID + h] = s;
        s = g_aggA[c * HID + h] * s + g_aggB[c * HID + h];
    }
}

// ---------------------------------------------------------------------------
// Scan phase 3: apply prefix, emit all hidden states.
// ---------------------------------------------------------------------------
__global__ __launch_bounds__(512) void scan_phase3(void)
{
    const int c = blockIdx.x;
    const int h = threadIdx.x;
    float s = g_pref[c * HID + h];
    size_t base = ((size_t)c * CHUNK_L) * HID + h;
    #pragma unroll 4
    for (int t = 0; t < CHUNK_L; t++) {
        float a = g_a[base];
        float b = g_b[base];
        s = a * s + b;
        g_s[base] = s;
        base += HID;
    }
}

// ---------------------------------------------------------------------------
// GEMM2: out = S * Wo^T + bo. Same tiling as GEMM1, single accumulator.
// ---------------------------------------------------------------------------
__global__ __launch_bounds__(256) void gemm_out_kernel(
    const float* __restrict__ Wo, const float* __restrict__ bo,
    float* __restrict__ out)
{
    __shared__ float Xs[32][128];
    __shared__ float Ws[32][64];

    const int tid = threadIdx.x;
    const int m0 = blockIdx.y * 128;
    const int n0 = blockIdx.x * 64;

    const int xr  = tid & 127;
    const int xc4 = (tid >> 7) * 4;
    const int wr  = tid & 63;
    const int wc4 = (tid >> 6) * 2;

    const int tx = tid & 15;
    const int ty = tid >> 4;

    float acc[8][4];
    #pragma unroll
    for (int i = 0; i < 8; i++)
        #pragma unroll
        for (int j = 0; j < 4; j++) acc[i][j] = 0.f;

    for (int k0 = 0; k0 < 512; k0 += 32) {
        #pragma unroll
        for (int j = 0; j < 4; j++) {
            const int kk = (xc4 + j) * 4;
            float4 v = *(const float4*)(g_s + (size_t)(m0 + xr) * 512 + k0 + kk);
            Xs[kk + 0][xr] = v.x; Xs[kk + 1][xr] = v.y;
            Xs[kk + 2][xr] = v.z; Xs[kk + 3][xr] = v.w;
        }
        #pragma unroll
        for (int j = 0; j < 2; j++) {
            const int kk = (wc4 + j) * 4;
            float4 vw = *(const float4*)(Wo + (size_t)(n0 + wr) * 512 + k0 + kk);
            Ws[kk + 0][wr] = vw.x; Ws[kk + 1][wr] = vw.y;
            Ws[kk + 2][wr] = vw.z; Ws[kk + 3][wr] = vw.w;
        }
        __syncthreads();

        #pragma unroll
        for (int k = 0; k < 32; k++) {
            float4 xa = *(const float4*)&Xs[k][ty * 8];
            float4 xb = *(const float4*)&Xs[k][ty * 8 + 4];
            float4 ww = *(const float4*)&Ws[k][tx * 4];
            float xm[8] = {xa.x, xa.y, xa.z, xa.w, xb.x, xb.y, xb.z, xb.w};
            float fw[4] = {ww.x, ww.y, ww.z, ww.w};
            #pragma unroll
            for (int i = 0; i < 8; i++)
                #pragma unroll
                for (int j = 0; j < 4; j++)
                    acc[i][j] += xm[i] * fw[j];
        }
        __syncthreads();
    }

    float bov[4];
    #pragma unroll
    for (int j = 0; j < 4; j++) bov[j] = bo[n0 + tx * 4 + j];

    #pragma unroll
    for (int i = 0; i < 8; i++) {
        const int m = m0 + ty * 8 + i;
        float4 ov;
        ov.x = acc[i][0] + bov[0];
        ov.y = acc[i][1] + bov[1];
        ov.z = acc[i][2] + bov[2];
        ov.w = acc[i][3] + bov[3];
        *(float4*)(out + (size_t)m * 512 + n0 + tx * 4) = ov;
    }
}

// ---------------------------------------------------------------------------
extern "C" void kernel_launch(void* const* d_in, const int* in_sizes, int n_in,
                              void* d_out, int out_size)
{
    const float* xs = (const float*)d_in[0];
    const float* Wz = (const float*)d_in[1];
    const float* bz = (const float*)d_in[2];
    const float* Wh = (const float*)d_in[3];
    const float* bh = (const float*)d_in[4];
    const float* Wo = (const float*)d_in[5];
    const float* bo = (const float*)d_in[6];
    float* out = (float*)d_out;

    dim3 g1(HID / 64, T_LEN / 128);
    gemm_zh_kernel<<<g1, 256>>>(xs, Wz, bz, Wh, bh);
    scan_phase1<<<NCHUNK, 512>>>();
    scan_phase2<<<1, 512>>>();
    scan_phase3<<<NCHUNK, 512>>>();
    dim3 g2(512 / 64, T_LEN / 128);
    gemm_out_kernel<<<g2, 256>>>(Wo, bo, out);
}

// round 3
// speedup vs baseline: 2.8335x; 2.8335x over previous
#include <cuda_runtime.h>
#include <cuda_fp16.h>
#include <cstdint>

#define T_LEN 16384
#define HID   512
#define NCHUNK 256
#define CHUNK_L 64
#define SA 40          // smem row stride in halves (32 used + 8 pad)

// ---------------------------------------------------------------------------
// Device scratch (no runtime allocation allowed)
// ---------------------------------------------------------------------------
__device__ __half g_xh[T_LEN * HID], g_xl[T_LEN * HID];
__device__ __half g_wzh[HID * HID], g_wzl[HID * HID];
__device__ __half g_whh[HID * HID], g_whl[HID * HID];
__device__ __half g_woh[HID * HID], g_wol[HID * HID];
__device__ float g_a[T_LEN * HID], g_b[T_LEN * HID];
__device__ __half g_sh[T_LEN * HID], g_sl[T_LEN * HID];
__device__ float g_aggA[NCHUNK * HID], g_aggB[NCHUNK * HID], g_pref[NCHUNK * HID];

// ---------------------------------------------------------------------------
// PTX helpers (all sm_80-era: valid under compute_103 virtual arch)
// ---------------------------------------------------------------------------
__device__ __forceinline__ uint32_t smem_u32(const void* p) {
    uint32_t a;
    asm("{ .reg .u64 t; cvta.to.shared.u64 t, %1; cvt.u32.u64 %0, t; }" : "=r"(a) : "l"(p));
    return a;
}

__device__ __forceinline__ void cp16(uint32_t dst, const void* src) {
    asm volatile("cp.async.ca.shared.global [%0], [%1], 16;" :: "r"(dst), "l"(src));
}
#define CP_COMMIT() asm volatile("cp.async.commit_group;" ::: "memory")
#define CP_WAIT1()  asm volatile("cp.async.wait_group 1;" ::: "memory")

__device__ __forceinline__ void ldm4(uint32_t* r, uint32_t addr) {
    asm volatile("ldmatrix.sync.aligned.m8n8.x4.shared.b16 {%0,%1,%2,%3}, [%4];"
                 : "=r"(r[0]), "=r"(r[1]), "=r"(r[2]), "=r"(r[3]) : "r"(addr));
}

__device__ __forceinline__ void mma16816(float* d, const uint32_t* a, uint32_t b0, uint32_t b1) {
    asm volatile(
        "mma.sync.aligned.m16n8k16.row.col.f32.f16.f16.f32 "
        "{%0,%1,%2,%3}, {%4,%5,%6,%7}, {%8,%9}, {%0,%1,%2,%3};"
        : "+f"(d[0]), "+f"(d[1]), "+f"(d[2]), "+f"(d[3])
        : "r"(a[0]), "r"(a[1]), "r"(a[2]), "r"(a[3]), "r"(b0), "r"(b1));
}

// ---------------------------------------------------------------------------
// fp32 -> fp16 hi/lo split (2 elems per thread, half2 stores)
// ---------------------------------------------------------------------------
__global__ __launch_bounds__(256) void convert_split(const float* __restrict__ s,
                                                     __half* __restrict__ hi,
                                                     __half* __restrict__ lo, int n2) {
    int i = blockIdx.x * 256 + threadIdx.x;
    if (i < n2) {
        float2 x = *(const float2*)(s + i * 2);
        __half h0 = __float2half(x.x), h1 = __float2half(x.y);
        __half l0 = __float2half(x.x - __half2float(h0));
        __half l1 = __float2half(x.y - __half2float(h1));
        *(__half2*)(hi + i * 2) = __halves2half2(h0, h1);
        *(__half2*)(lo + i * 2) = __halves2half2(l0, l1);
    }
}

// ---------------------------------------------------------------------------
// GEMM1: Z = X Wz^T + bz, Hc = X Wh^T + bh -> g_a = 1-sig(Z), g_b = sig(Z)*Hc
// 3 K-phases (fp16 split): (Xh,Wh) (Xh,Wl) (Xl,Wh).  BM=128 BN=64 BK=32.
// ---------------------------------------------------------------------------
#define NIT 48  // 3 phases * 16 chunks

__device__ __forceinline__ void g1_load(int it, int st, int m0, int n0, int tid,
                                        uint32_t sA, uint32_t sBz, uint32_t sBh) {
    const int ph = it >> 4, k0 = (it & 15) << 5;
    const __half* pa = (ph == 2) ? g_xl : g_xh;
    const __half* pz = (ph == 1) ? g_wzl : g_wzh;
    const __half* pw = (ph == 1) ? g_whl : g_whh;
    #pragma unroll
    for (int j = 0; j < 2; j++) {
        const int ch = tid + j * 256, row = ch >> 2, c = ch & 3;
        cp16(sA + st * 10240 + (row * SA + c * 8) * 2,
             pa + (size_t)(m0 + row) * HID + k0 + c * 8);
    }
    const int row = tid >> 2, c = tid & 3;
    cp16(sBz + st * 5120 + (row * SA + c * 8) * 2,
         pz + (size_t)(n0 + row) * HID + k0 + c * 8);
    cp16(sBh + st * 5120 + (row * SA + c * 8) * 2,
         pw + (size_t)(n0 + row) * HID + k0 + c * 8);
}

__global__ __launch_bounds__(256) void gemm1_kernel(const float* __restrict__ bz,
                                                    const float* __restrict__ bh) {
    __shared__ __half As[2 * 128 * SA];
    __shared__ __half Bzs[2 * 64 * SA];
    __shared__ __half Bhs[2 * 64 * SA];
    const int tid = threadIdx.x, wid = tid >> 5, l = tid & 31;
    const int wm = wid & 3, wn = wid >> 2;
    const int m0 = blockIdx.y * 128, n0 = blockIdx.x * 64;

    const uint32_t sA = smem_u32(As), sBz = smem_u32(Bzs), sBh = smem_u32(Bhs);
    const uint32_t aoff = ((wm * 32 + (l & 15)) * SA + (l >> 4) * 8) * 2;
    const uint32_t boff = ((wn * 32 + (l & 15)) * SA + (l >> 4) * 8) * 2;

    float accZ[2][4][4] = {}, accH[2][4][4] = {};

    g1_load(0, 0, m0, n0, tid, sA, sBz, sBh); CP_COMMIT();
    g1_load(1, 1, m0, n0, tid, sA, sBz, sBh); CP_COMMIT();

    #pragma unroll 1
    for (int it = 0; it < NIT; it++) {
        const int st = it & 1;
        CP_WAIT1();
        __syncthreads();
        const uint32_t bA = sA + st * 10240, bZ = sBz + st * 5120, bH = sBh + st * 5120;
        #pragma unroll
        for (int k16 = 0; k16 < 2; k16++) {
            uint32_t a[2][4], vz[2][4], vh[2][4];
            ldm4(a[0], bA + aoff + k16 * 32);
            ldm4(a[1], bA + aoff + 16 * SA * 2 + k16 * 32);
            ldm4(vz[0], bZ + boff + k16 * 32);
            ldm4(vz[1], bZ + boff + 16 * SA * 2 + k16 * 32);
            ldm4(vh[0], bH + boff + k16 * 32);
            ldm4(vh[1], bH + boff + 16 * SA * 2 + k16 * 32);
            #pragma unroll
            for (int mt = 0; mt < 2; mt++)
                #pragma unroll
                for (int nt = 0; nt < 4; nt++) {
                    const int p = nt >> 1, s = nt & 1;
                    mma16816(accZ[mt][nt], a[mt], vz[p][s], vz[p][s + 2]);
                    mma16816(accH[mt][nt], a[mt], vh[p][s], vh[p][s + 2]);
                }
        }
        __syncthreads();
        if (it + 2 < NIT) g1_load(it + 2, st, m0, n0, tid, sA, sBz, sBh);
        CP_COMMIT();
    }

    // epilogue: a = 1 - sigmoid(z), b = sigmoid(z) * h
    #pragma unroll
    for (int mt = 0; mt < 2; mt++) {
        const int row = m0 + wm * 32 + mt * 16 + (l >> 2);
        #pragma unroll
        for (int nt = 0; nt < 4; nt++) {
            const int col = n0 + wn * 32 + nt * 8 + (l & 3) * 2;
            const float bz0 = __ldg(bz + col), bz1 = __ldg(bz + col + 1);
            const float bh0 = __ldg(bh + col), bh1 = __ldg(bh + col + 1);
            float z[4] = {accZ[mt][nt][0] + bz0, accZ[mt][nt][1] + bz1,
                          accZ[mt][nt][2] + bz0, accZ[mt][nt][3] + bz1};
            float h[4] = {accH[mt][nt][0] + bh0, accH[mt][nt][1] + bh1,
                          accH[mt][nt][2] + bh0, accH[mt][nt][3] + bh1};
            float sg[4];
            #pragma unroll
            for (int q = 0; q < 4; q++) sg[q] = 1.f / (1.f + __expf(-z[q]));
            *(float2*)(g_a + (size_t)row * HID + col) = make_float2(1.f - sg[0], 1.f - sg[1]);
            *(float2*)(g_b + (size_t)row * HID + col) = make_float2(sg[0] * h[0], sg[1] * h[1]);
            *(float2*)(g_a + (size_t)(row + 8) * HID + col) = make_float2(1.f - sg[2], 1.f - sg[3]);
            *(float2*)(g_b + (size_t)(row + 8) * HID + col) = make_float2(sg[2] * h[2], sg[3] * h[3]);
        }
    }
}

// ---------------------------------------------------------------------------
// GEMM2: out = S Wo^T + bo.  Phases: (Sh,Woh) (Sh,Wol) (Sl,Woh).
// ---------------------------------------------------------------------------
__device__ __forceinline__ void g2_load(int it, int st, int m0, int n0, int tid,
                                        uint32_t sA, uint32_t sB) {
    const int ph = it >> 4, k0 = (it & 15) << 5;
    const __half* pa = (ph == 2) ? g_sl : g_sh;
    const __half* pb = (ph == 1) ? g_wol : g_woh;
    #pragma unroll
    for (int j = 0; j < 2; j++) {
        const int ch = tid + j * 256, row = ch >> 2, c = ch & 3;
        cp16(sA + st * 10240 + (row * SA + c * 8) * 2,
             pa + (size_t)(m0 + row) * HID + k0 + c * 8);
    }
    const int row = tid >> 2, c = tid & 3;
    cp16(sB + st * 5120 + (row * SA + c * 8) * 2,
         pb + (size_t)(n0 + row) * HID + k0 + c * 8);
}

__global__ __launch_bounds__(256) void gemm2_kernel(const float* __restrict__ bo,
                                                    float* __restrict__ out) {
    __shared__ __half As[2 * 128 * SA];
    __shared__ __half Bs[2 * 64 * SA];
    const int tid = threadIdx.x, wid = tid >> 5, l = tid & 31;
    const int wm = wid & 3, wn = wid >> 2;
    const int m0 = blockIdx.y * 128, n0 = blockIdx.x * 64;

    const uint32_t sA = smem_u32(As), sB = smem_u32(Bs);
    const uint32_t aoff = ((wm * 32 + (l & 15)) * SA + (l >> 4) * 8) * 2;
    const uint32_t boff = ((wn * 32 + (l & 15)) * SA + (l >> 4) * 8) * 2;

    float acc[2][4][4] = {};

    g2_load(0, 0, m0, n0, tid, sA, sB); CP_COMMIT();
    g2_load(1, 1, m0, n0, tid, sA, sB); CP_COMMIT();

    #pragma unroll 1
    for (int it = 0; it < NIT; it++) {
        const int st = it & 1;
        CP_WAIT1();
        __syncthreads();
        const uint32_t bA = sA + st * 10240, bB = sB + st * 5120;
        #pragma unroll
        for (int k16 = 0; k16 < 2; k16++) {
            uint32_t a[2][4], vb[2][4];
            ldm4(a[0], bA + aoff + k16 * 32);
            ldm4(a[1], bA + aoff + 16 * SA * 2 + k16 * 32);
            ldm4(vb[0], bB + boff + k16 * 32);
            ldm4(vb[1], bB + boff + 16 * SA * 2 + k16 * 32);
            #pragma unroll
            for (int mt = 0; mt < 2; mt++)
                #pragma unroll
                for (int nt = 0; nt < 4; nt++) {
                    const int p = nt >> 1, s = nt & 1;
                    mma16816(acc[mt][nt], a[mt], vb[p][s], vb[p][s + 2]);
                }
        }
        __syncthreads();
        if (it + 2 < NIT) g2_load(it + 2, st, m0, n0, tid, sA, sB);
        CP_COMMIT();
    }

    #pragma unroll
    for (int mt = 0; mt < 2; mt++) {
        const int row = m0 + wm * 32 + mt * 16 + (l >> 2);
        #pragma unroll
        for (int nt = 0; nt < 4; nt++) {
            const int col = n0 + wn * 32 + nt * 8 + (l & 3) * 2;
            const float b0 = __ldg(bo + col), b1 = __ldg(bo + col + 1);
            *(float2*)(out + (size_t)row * HID + col) =
                make_float2(acc[mt][nt][0] + b0, acc[mt][nt][1] + b1);
            *(float2*)(out + (size_t)(row + 8) * HID + col) =
                make_float2(acc[mt][nt][2] + b0, acc[mt][nt][3] + b1);
        }
    }
}

// ---------------------------------------------------------------------------
// Scan phases: s_t = a_t * s_{t-1} + b_t, chunked
// ---------------------------------------------------------------------------
__global__ __launch_bounds__(256) void scan_phase1() {
    const int c = blockIdx.x;
    const int h = blockIdx.y * 256 + threadIdx.x;
    float A = 1.f, B = 0.f;
    size_t base = (size_t)c * CHUNK_L * HID + h;
    #pragma unroll 8
    for (int t = 0; t < CHUNK_L; t++) {
        const float a = g_a[base];
        const float b = g_b[base];
        A = a * A;
        B = a * B + b;
        base += HID;
    }
    g_aggA[c * HID + h] = A;
    g_aggB[c * HID + h] = B;
}

__global__ __launch_bounds__(512) void scan_phase2() {
    const int h = threadIdx.x;
    float s = 0.f;
    #pragma unroll 8
    for (int c = 0; c < NCHUNK; c++) {
        g_pref[c * HID + h] = s;
        s = g_aggA[c * HID + h] * s + g_aggB[c * HID + h];
    }
}

__global__ __launch_bounds__(256) void scan_phase3() {
    const int c = blockIdx.x;
    const int h = blockIdx.y * 256 + threadIdx.x;
    float s = g_pref[c * HID + h];
    size_t base = (size_t)c * CHUNK_L * HID + h;
    #pragma unroll 8
    for (int t = 0; t < CHUNK_L; t++) {
        const float a = g_a[base];
        const float b = g_b[base];
        s = a * s + b;
        const __half hi = __float2half(s);
        g_sh[base] = hi;
        g_sl[base] = __float2half(s - __half2float(hi));
        base += HID;
    }
}

// ---------------------------------------------------------------------------
extern "C" void kernel_launch(void* const* d_in, const int* in_sizes, int n_in,
                              void* d_out, int out_size) {
    const float* xs = (const float*)d_in[0];
    const float* Wz = (const float*)d_in[1];
    const float* bz = (const float*)d_in[2];
    const float* Wh = (const float*)d_in[3];
    const float* bh = (const float*)d_in[4];
    const float* Wo = (const float*)d_in[5];
    const float* bo = (const float*)d_in[6];
    float* out = (float*)d_out;

    __half *xh, *xl, *wzh, *wzl, *whh, *whl, *woh, *wol;
    cudaGetSymbolAddress((void**)&xh, g_xh);
    cudaGetSymbolAddress((void**)&xl, g_xl);
    cudaGetSymbolAddress((void**)&wzh, g_wzh);
    cudaGetSymbolAddress((void**)&wzl, g_wzl);
    cudaGetSymbolAddress((void**)&whh, g_whh);
    cudaGetSymbolAddress((void**)&whl, g_whl);
    cudaGetSymbolAddress((void**)&woh, g_woh);
    cudaGetSymbolAddress((void**)&wol, g_wol);

    const int nX2 = T_LEN * HID / 2, nW2 = HID * HID / 2;
    convert_split<<<(nX2 + 255) / 256, 256>>>(xs, xh, xl, nX2);
    convert_split<<<(nW2 + 255) / 256, 256>>>(Wz, wzh, wzl, nW2);
    convert_split<<<(nW2 + 255) / 256, 256>>>(Wh, whh, whl, nW2);
    convert_split<<<(nW2 + 255) / 256, 256>>>(Wo, woh, wol, nW2);

    gemm1_kernel<<<dim3(HID / 64, T_LEN / 128), 256>>>(bz, bh);

    scan_phase1<<<dim3(NCHUNK, 2), 256>>>();
    scan_phase2<<<1, 512>>>();
    scan_phase3<<<dim3(NCHUNK, 2), 256>>>();

    gemm2_kernel<<<dim3(HID / 64, T_LEN / 128), 256>>>(bo, out);
}

// round 4
// speedup vs baseline: 3.6000x; 1.2705x over previous
#include <cuda_runtime.h>
#include <cuda_fp16.h>
#include <cstdint>

#define T_LEN 16384
#define HID   512
#define NCHUNK 256
#define CHUNK_L 64
#define SA 40          // smem row stride in halves (32 used + 8 pad)

// ---------------------------------------------------------------------------
// Device scratch (no runtime allocation allowed)
// ---------------------------------------------------------------------------
__device__ __half g_xh[T_LEN * HID];
__device__ __half g_wzh[HID * HID], g_wzl[HID * HID];
__device__ __half g_whh[HID * HID], g_whl[HID * HID];
__device__ __half g_woh[HID * HID], g_wol[HID * HID];
__device__ float g_a[T_LEN * HID], g_b[T_LEN * HID];
__device__ __half g_sh[T_LEN * HID];
__device__ float g_aggA[NCHUNK * HID], g_aggB[NCHUNK * HID], g_pref[NCHUNK * HID];

// ---------------------------------------------------------------------------
// PTX helpers (sm_80-era: valid under compute_103 virtual arch)
// ---------------------------------------------------------------------------
__device__ __forceinline__ uint32_t smem_u32(const void* p) {
    uint32_t a;
    asm("{ .reg .u64 t; cvta.to.shared.u64 t, %1; cvt.u32.u64 %0, t; }" : "=r"(a) : "l"(p));
    return a;
}

__device__ __forceinline__ void cp16(uint32_t dst, const void* src) {
    asm volatile("cp.async.ca.shared.global [%0], [%1], 16;" :: "r"(dst), "l"(src));
}
#define CP_COMMIT() asm volatile("cp.async.commit_group;" ::: "memory")
#define CP_WAIT1()  asm volatile("cp.async.wait_group 1;" ::: "memory")

__device__ __forceinline__ void ldm4(uint32_t* r, uint32_t addr) {
    asm volatile("ldmatrix.sync.aligned.m8n8.x4.shared.b16 {%0,%1,%2,%3}, [%4];"
                 : "=r"(r[0]), "=r"(r[1]), "=r"(r[2]), "=r"(r[3]) : "r"(addr));
}

__device__ __forceinline__ void mma16816(float* d, const uint32_t* a, uint32_t b0, uint32_t b1) {
    asm volatile(
        "mma.sync.aligned.m16n8k16.row.col.f32.f16.f16.f32 "
        "{%0,%1,%2,%3}, {%4,%5,%6,%7}, {%8,%9}, {%0,%1,%2,%3};"
        : "+f"(d[0]), "+f"(d[1]), "+f"(d[2]), "+f"(d[3])
        : "r"(a[0]), "r"(a[1]), "r"(a[2]), "r"(a[3]), "r"(b0), "r"(b1));
}

// ---------------------------------------------------------------------------
// Converters
// ---------------------------------------------------------------------------
__global__ __launch_bounds__(256) void convert_hi(const float* __restrict__ s,
                                                  __half* __restrict__ hi, int n2) {
    int i = blockIdx.x * 256 + threadIdx.x;
    if (i < n2) {
        float2 x = *(const float2*)(s + i * 2);
        *(__half2*)(hi + i * 2) = __halves2half2(__float2half(x.x), __float2half(x.y));
    }
}

__global__ __launch_bounds__(256) void convert_split(const float* __restrict__ s,
                                                     __half* __restrict__ hi,
                                                     __half* __restrict__ lo, int n2) {
    int i = blockIdx.x * 256 + threadIdx.x;
    if (i < n2) {
        float2 x = *(const float2*)(s + i * 2);
        __half h0 = __float2half(x.x), h1 = __float2half(x.y);
        __half l0 = __float2half(x.x - __half2float(h0));
        __half l1 = __float2half(x.y - __half2float(h1));
        *(__half2*)(hi + i * 2) = __halves2half2(h0, h1);
        *(__half2*)(lo + i * 2) = __halves2half2(l0, l1);
    }
}

// ---------------------------------------------------------------------------
// GEMM1: Z = X Wz^T + bz, Hc = X Wh^T + bh -> g_a = 1-sig(Z), g_b = sig(Z)*Hc
// 2 K-phases: (Xh,Wh) (Xh,Wl).  BM=128 BN=64 BK=32.
// ---------------------------------------------------------------------------
#define NIT 32  // 2 phases * 16 chunks

__device__ __forceinline__ void g1_load(int it, int st, int m0, int n0, int tid,
                                        uint32_t sA, uint32_t sBz, uint32_t sBh) {
    const int ph = it >> 4, k0 = (it & 15) << 5;
    const __half* pz = ph ? g_wzl : g_wzh;
    const __half* pw = ph ? g_whl : g_whh;
    #pragma unroll
    for (int j = 0; j < 2; j++) {
        const int ch = tid + j * 256, row = ch >> 2, c = ch & 3;
        cp16(sA + st * 10240 + (row * SA + c * 8) * 2,
             g_xh + (size_t)(m0 + row) * HID + k0 + c * 8);
    }
    const int row = tid >> 2, c = tid & 3;
    cp16(sBz + st * 5120 + (row * SA + c * 8) * 2,
         pz + (size_t)(n0 + row) * HID + k0 + c * 8);
    cp16(sBh + st * 5120 + (row * SA + c * 8) * 2,
         pw + (size_t)(n0 + row) * HID + k0 + c * 8);
}

__global__ __launch_bounds__(256) void gemm1_kernel(const float* __restrict__ bz,
                                                    const float* __restrict__ bh) {
    __shared__ __half As[2 * 128 * SA];
    __shared__ __half Bzs[2 * 64 * SA];
    __shared__ __half Bhs[2 * 64 * SA];
    const int tid = threadIdx.x, wid = tid >> 5, l = tid & 31;
    const int wm = wid & 3, wn = wid >> 2;
    const int m0 = blockIdx.y * 128, n0 = blockIdx.x * 64;

    const uint32_t sA = smem_u32(As), sBz = smem_u32(Bzs), sBh = smem_u32(Bhs);
    const uint32_t aoff = ((wm * 32 + (l & 15)) * SA + (l >> 4) * 8) * 2;
    const uint32_t boff = ((wn * 32 + (l & 15)) * SA + (l >> 4) * 8) * 2;

    float accZ[2][4][4] = {}, accH[2][4][4] = {};

    g1_load(0, 0, m0, n0, tid, sA, sBz, sBh); CP_COMMIT();
    g1_load(1, 1, m0, n0, tid, sA, sBz, sBh); CP_COMMIT();

    #pragma unroll 1
    for (int it = 0; it < NIT; it++) {
        const int st = it & 1;
        CP_WAIT1();
        __syncthreads();
        const uint32_t bA = sA + st * 10240, bZ = sBz + st * 5120, bH = sBh + st * 5120;
        #pragma unroll
        for (int k16 = 0; k16 < 2; k16++) {
            uint32_t a[2][4], vz[2][4], vh[2][4];
            ldm4(a[0], bA + aoff + k16 * 32);
            ldm4(a[1], bA + aoff + 16 * SA * 2 + k16 * 32);
            ldm4(vz[0], bZ + boff + k16 * 32);
            ldm4(vz[1], bZ + boff + 16 * SA * 2 + k16 * 32);
            ldm4(vh[0], bH + boff + k16 * 32);
            ldm4(vh[1], bH + boff + 16 * SA * 2 + k16 * 32);
            #pragma unroll
            for (int mt = 0; mt < 2; mt++)
                #pragma unroll
                for (int nt = 0; nt < 4; nt++) {
                    const int p = nt >> 1, s = nt & 1;
                    mma16816(accZ[mt][nt], a[mt], vz[p][s], vz[p][s + 2]);
                    mma16816(accH[mt][nt], a[mt], vh[p][s], vh[p][s + 2]);
                }
        }
        __syncthreads();
        if (it + 2 < NIT) g1_load(it + 2, st, m0, n0, tid, sA, sBz, sBh);
        CP_COMMIT();
    }

    // epilogue: a = 1 - sigmoid(z), b = sigmoid(z) * h
    #pragma unroll
    for (int mt = 0; mt < 2; mt++) {
        const int row = m0 + wm * 32 + mt * 16 + (l >> 2);
        #pragma unroll
        for (int nt = 0; nt < 4; nt++) {
            const int col = n0 + wn * 32 + nt * 8 + (l & 3) * 2;
            const float bz0 = __ldg(bz + col), bz1 = __ldg(bz + col + 1);
            const float bh0 = __ldg(bh + col), bh1 = __ldg(bh + col + 1);
            float z[4] = {accZ[mt][nt][0] + bz0, accZ[mt][nt][1] + bz1,
                          accZ[mt][nt][2] + bz0, accZ[mt][nt][3] + bz1};
            float h[4] = {accH[mt][nt][0] + bh0, accH[mt][nt][1] + bh1,
                          accH[mt][nt][2] + bh0, accH[mt][nt][3] + bh1};
            float sg[4];
            #pragma unroll
            for (int q = 0; q < 4; q++) sg[q] = 1.f / (1.f + __expf(-z[q]));
            *(float2*)(g_a + (size_t)row * HID + col) = make_float2(1.f - sg[0], 1.f - sg[1]);
            *(float2*)(g_b + (size_t)row * HID + col) = make_float2(sg[0] * h[0], sg[1] * h[1]);
            *(float2*)(g_a + (size_t)(row + 8) * HID + col) = make_float2(1.f - sg[2], 1.f - sg[3]);
            *(float2*)(g_b + (size_t)(row + 8) * HID + col) = make_float2(sg[2] * h[2], sg[3] * h[3]);
        }
    }
}

// ---------------------------------------------------------------------------
// GEMM2: out = S Wo^T + bo.  2 phases: (Sh,Woh) (Sh,Wol).
// ---------------------------------------------------------------------------
__device__ __forceinline__ void g2_load(int it, int st, int m0, int n0, int tid,
                                        uint32_t sA, uint32_t sB) {
    const int ph = it >> 4, k0 = (it & 15) << 5;
    const __half* pb = ph ? g_wol : g_woh;
    #pragma unroll
    for (int j = 0; j < 2; j++) {
        const int ch = tid + j * 256, row = ch >> 2, c = ch & 3;
        cp16(sA + st * 10240 + (row * SA + c * 8) * 2,
             g_sh + (size_t)(m0 + row) * HID + k0 + c * 8);
    }
    const int row = tid >> 2, c = tid & 3;
    cp16(sB + st * 5120 + (row * SA + c * 8) * 2,
         pb + (size_t)(n0 + row) * HID + k0 + c * 8);
}

__global__ __launch_bounds__(256) void gemm2_kernel(const float* __restrict__ bo,
                                                    float* __restrict__ out) {
    __shared__ __half As[2 * 128 * SA];
    __shared__ __half Bs[2 * 64 * SA];
    const int tid = threadIdx.x, wid = tid >> 5, l = tid & 31;
    const int wm = wid & 3, wn = wid >> 2;
    const int m0 = blockIdx.y * 128, n0 = blockIdx.x * 64;

    const uint32_t sA = smem_u32(As), sB = smem_u32(Bs);
    const uint32_t aoff = ((wm * 32 + (l & 15)) * SA + (l >> 4) * 8) * 2;
    const uint32_t boff = ((wn * 32 + (l & 15)) * SA + (l >> 4) * 8) * 2;

    float acc[2][4][4] = {};

    g2_load(0, 0, m0, n0, tid, sA, sB); CP_COMMIT();
    g2_load(1, 1, m0, n0, tid, sA, sB); CP_COMMIT();

    #pragma unroll 1
    for (int it = 0; it < NIT; it++) {
        const int st = it & 1;
        CP_WAIT1();
        __syncthreads();
        const uint32_t bA = sA + st * 10240, bB = sB + st * 5120;
        #pragma unroll
        for (int k16 = 0; k16 < 2; k16++) {
            uint32_t a[2][4], vb[2][4];
            ldm4(a[0], bA + aoff + k16 * 32);
            ldm4(a[1], bA + aoff + 16 * SA * 2 + k16 * 32);
            ldm4(vb[0], bB + boff + k16 * 32);
            ldm4(vb[1], bB + boff + 16 * SA * 2 + k16 * 32);
            #pragma unroll
            for (int mt = 0; mt < 2; mt++)
                #pragma unroll
                for (int nt = 0; nt < 4; nt++) {
                    const int p = nt >> 1, s = nt & 1;
                    mma16816(acc[mt][nt], a[mt], vb[p][s], vb[p][s + 2]);
                }
        }
        __syncthreads();
        if (it + 2 < NIT) g2_load(it + 2, st, m0, n0, tid, sA, sB);
        CP_COMMIT();
    }

    #pragma unroll
    for (int mt = 0; mt < 2; mt++) {
        const int row = m0 + wm * 32 + mt * 16 + (l >> 2);
        #pragma unroll
        for (int nt = 0; nt < 4; nt++) {
            const int col = n0 + wn * 32 + nt * 8 + (l & 3) * 2;
            const float b0 = __ldg(bo + col), b1 = __ldg(bo + col + 1);
            *(float2*)(out + (size_t)row * HID + col) =
                make_float2(acc[mt][nt][0] + b0, acc[mt][nt][1] + b1);
            *(float2*)(out + (size_t)(row + 8) * HID + col) =
                make_float2(acc[mt][nt][2] + b0, acc[mt][nt][3] + b1);
        }
    }
}

// ---------------------------------------------------------------------------
// Scan phases: s_t = a_t * s_{t-1} + b_t, chunked
// ---------------------------------------------------------------------------
__global__ __launch_bounds__(256) void scan_phase1() {
    const int c = blockIdx.x;
    const int h = blockIdx.y * 256 + threadIdx.x;
    float A = 1.f, B = 0.f;
    size_t base = (size_t)c * CHUNK_L * HID + h;
    #pragma unroll 8
    for (int t = 0; t < CHUNK_L; t++) {
        const float a = g_a[base];
        const float b = g_b[base];
        A = a * A;
        B = a * B + b;
        base += HID;
    }
    g_aggA[c * HID + h] = A;
    g_aggB[c * HID + h] = B;
}

__global__ __launch_bounds__(512) void scan_phase2() {
    const int h = threadIdx.x;
    float s = 0.f;
    #pragma unroll 8
    for (int c = 0; c < NCHUNK; c++) {
        g_pref[c * HID + h] = s;
        s = g_aggA[c * HID + h] * s + g_aggB[c * HID + h];
    }
}

__global__ __launch_bounds__(256) void scan_phase3() {
    const int c = blockIdx.x;
    const int h = blockIdx.y * 256 + threadIdx.x;
    float s = g_pref[c * HID + h];
    size_t base = (size_t)c * CHUNK_L * HID + h;
    #pragma unroll 8
    for (int t = 0; t < CHUNK_L; t++) {
        const float a = g_a[base];
        const float b = g_b[base];
        s = a * s + b;
        g_sh[base] = __float2half(s);
        base += HID;
    }
}

// ---------------------------------------------------------------------------
extern "C" void kernel_launch(void* const* d_in, const int* in_sizes, int n_in,
                              void* d_out, int out_size) {
    const float* xs = (const float*)d_in[0];
    const float* Wz = (const float*)d_in[1];
    const float* bz = (const float*)d_in[2];
    const float* Wh = (const float*)d_in[3];
    const float* bh = (const float*)d_in[4];
    const float* Wo = (const float*)d_in[5];
    const float* bo = (const float*)d_in[6];
    float* out = (float*)d_out;

    __half *xh, *wzh, *wzl, *whh, *whl, *woh, *wol;
    cudaGetSymbolAddress((void**)&xh, g_xh);
    cudaGetSymbolAddress((void**)&wzh, g_wzh);
    cudaGetSymbolAddress((void**)&wzl, g_wzl);
    cudaGetSymbolAddress((void**)&whh, g_whh);
    cudaGetSymbolAddress((void**)&whl, g_whl);
    cudaGetSymbolAddress((void**)&woh, g_woh);
    cudaGetSymbolAddress((void**)&wol, g_wol);

    const int nX2 = T_LEN * HID / 2, nW2 = HID * HID / 2;
    convert_hi<<<(nX2 + 255) / 256, 256>>>(xs, xh, nX2);
    convert_split<<<(nW2 + 255) / 256, 256>>>(Wz, wzh, wzl, nW2);
    convert_split<<<(nW2 + 255) / 256, 256>>>(Wh, whh, whl, nW2);
    convert_split<<<(nW2 + 255) / 256, 256>>>(Wo, woh, wol, nW2);

    gemm1_kernel<<<dim3(HID / 64, T_LEN / 128), 256>>>(bz, bh);

    scan_phase1<<<dim3(NCHUNK, 2), 256>>>();
    scan_phase2<<<1, 512>>>();
    scan_phase3<<<dim3(NCHUNK, 2), 256>>>();

    gemm2_kernel<<<dim3(HID / 64, T_LEN / 128), 256>>>(bo, out);
}

// round 5
// speedup vs baseline: 4.4214x; 1.2282x over previous
#include <cuda_runtime.h>
#include <cuda_fp16.h>
#include <cstdint>

#define T_LEN 16384
#define HID   512
#define NCHUNK 256
#define CHUNK_L 64
#define SA 40          // smem row stride in halves (32 used + 8 pad)

// ---------------------------------------------------------------------------
// Device scratch (no runtime allocation allowed)
// ---------------------------------------------------------------------------
__device__ __half g_xh[T_LEN * HID];
__device__ __half g_wzh[HID * HID], g_wzl[HID * HID];
__device__ __half g_whh[HID * HID], g_whl[HID * HID];
__device__ __half g_woh[HID * HID], g_wol[HID * HID];
__device__ float2 g_ab[T_LEN * HID];      // (a, b) interleaved
__device__ __half g_sh[T_LEN * HID];
__device__ float2 g_agg[NCHUNK * HID];    // (A, B) per chunk
__device__ float g_pref[NCHUNK * HID];

// ---------------------------------------------------------------------------
// PTX helpers (sm_80-era: valid under compute_103 virtual arch)
// ---------------------------------------------------------------------------
__device__ __forceinline__ uint32_t smem_u32(const void* p) {
    uint32_t a;
    asm("{ .reg .u64 t; cvta.to.shared.u64 t, %1; cvt.u32.u64 %0, t; }" : "=r"(a) : "l"(p));
    return a;
}

__device__ __forceinline__ void cp16(uint32_t dst, const void* src) {
    asm volatile("cp.async.ca.shared.global [%0], [%1], 16;" :: "r"(dst), "l"(src));
}
#define CP_COMMIT() asm volatile("cp.async.commit_group;" ::: "memory")
#define CP_WAIT1()  asm volatile("cp.async.wait_group 1;" ::: "memory")

__device__ __forceinline__ void ldm4(uint32_t* r, uint32_t addr) {
    asm volatile("ldmatrix.sync.aligned.m8n8.x4.shared.b16 {%0,%1,%2,%3}, [%4];"
                 : "=r"(r[0]), "=r"(r[1]), "=r"(r[2]), "=r"(r[3]) : "r"(addr));
}

__device__ __forceinline__ void mma16816(float* d, const uint32_t* a, uint32_t b0, uint32_t b1) {
    asm volatile(
        "mma.sync.aligned.m16n8k16.row.col.f32.f16.f16.f32 "
        "{%0,%1,%2,%3}, {%4,%5,%6,%7}, {%8,%9}, {%0,%1,%2,%3};"
        : "+f"(d[0]), "+f"(d[1]), "+f"(d[2]), "+f"(d[3])
        : "r"(a[0]), "r"(a[1]), "r"(a[2]), "r"(a[3]), "r"(b0), "r"(b1));
}

// ---------------------------------------------------------------------------
// Converters
// ---------------------------------------------------------------------------
__global__ __launch_bounds__(256) void convert_hi(const float* __restrict__ s,
                                                  __half* __restrict__ hi, int n2) {
    int i = blockIdx.x * 256 + threadIdx.x;
    if (i < n2) {
        float2 x = *(const float2*)(s + i * 2);
        *(__half2*)(hi + i * 2) = __halves2half2(__float2half(x.x), __float2half(x.y));
    }
}

__global__ __launch_bounds__(256) void convert_split(const float* __restrict__ s,
                                                     __half* __restrict__ hi,
                                                     __half* __restrict__ lo, int n2) {
    int i = blockIdx.x * 256 + threadIdx.x;
    if (i < n2) {
        float2 x = *(const float2*)(s + i * 2);
        __half h0 = __float2half(x.x), h1 = __float2half(x.y);
        __half l0 = __float2half(x.x - __half2float(h0));
        __half l1 = __float2half(x.y - __half2float(h1));
        *(__half2*)(hi + i * 2) = __halves2half2(h0, h1);
        *(__half2*)(lo + i * 2) = __halves2half2(l0, l1);
    }
}

// ---------------------------------------------------------------------------
// GEMM1: Z = X Wzh^T + X Wzl^T + bz ; Hc likewise. Single K pass, A shared
// between hi and lo weight products. BM=128 BN=64 BK=32, 16 chunks.
// smem/stage: A 10240B + 4 x B 5120B = 30720B; 2 stages -> dynamic smem.
// ---------------------------------------------------------------------------
#define G1_STG 30720
#define G1_BZH 10240
#define G1_BZL 15360
#define G1_BHH 20480
#define G1_BHL 25600

__device__ __forceinline__ void g1_load(int chunk, int st, int m0, int n0, int tid,
                                        uint32_t s) {
    const int k0 = chunk << 5;
    const uint32_t base = s + st * G1_STG;
    #pragma unroll
    for (int j = 0; j < 2; j++) {
        const int ch = tid + j * 256, row = ch >> 2, c = ch & 3;
        cp16(base + (row * SA + c * 8) * 2,
             g_xh + (size_t)(m0 + row) * HID + k0 + c * 8);
    }
    const int row = tid >> 2, c = tid & 3;
    const uint32_t off = (row * SA + c * 8) * 2;
    const size_t gsrc = (size_t)(n0 + row) * HID + k0 + c * 8;
    cp16(base + G1_BZH + off, g_wzh + gsrc);
    cp16(base + G1_BZL + off, g_wzl + gsrc);
    cp16(base + G1_BHH + off, g_whh + gsrc);
    cp16(base + G1_BHL + off, g_whl + gsrc);
}

__global__ __launch_bounds__(256) void gemm1_kernel(const float* __restrict__ bz,
                                                    const float* __restrict__ bh) {
    extern __shared__ __half S1[];
    const int tid = threadIdx.x, wid = tid >> 5, l = tid & 31;
    const int wm = wid & 3, wn = wid >> 2;
    const int m0 = blockIdx.y * 128, n0 = blockIdx.x * 64;

    const uint32_t s = smem_u32(S1);
    const uint32_t aoff = ((wm * 32 + (l & 15)) * SA + (l >> 4) * 8) * 2;
    const uint32_t boff = ((wn * 32 + (l & 15)) * SA + (l >> 4) * 8) * 2;

    float accZ[2][4][4] = {}, accH[2][4][4] = {};

    g1_load(0, 0, m0, n0, tid, s); CP_COMMIT();
    g1_load(1, 1, m0, n0, tid, s); CP_COMMIT();

    #pragma unroll 1
    for (int it = 0; it < 16; it++) {
        const int st = it & 1;
        CP_WAIT1();
        __syncthreads();
        const uint32_t bS = s + st * G1_STG;
        #pragma unroll
        for (int k16 = 0; k16 < 2; k16++) {
            uint32_t a[2][4], v[2][4];
            ldm4(a[0], bS + aoff + k16 * 32);
            ldm4(a[1], bS + aoff + 16 * SA * 2 + k16 * 32);
            // Z: hi then lo weights, same A frags
            ldm4(v[0], bS + G1_BZH + boff + k16 * 32);
            ldm4(v[1], bS + G1_BZH + boff + 16 * SA * 2 + k16 * 32);
            #pragma unroll
            for (int mt = 0; mt < 2; mt++)
                #pragma unroll
                for (int nt = 0; nt < 4; nt++)
                    mma16816(accZ[mt][nt], a[mt], v[nt >> 1][nt & 1], v[nt >> 1][(nt & 1) + 2]);
            ldm4(v[0], bS + G1_BZL + boff + k16 * 32);
            ldm4(v[1], bS + G1_BZL + boff + 16 * SA * 2 + k16 * 32);
            #pragma unroll
            for (int mt = 0; mt < 2; mt++)
                #pragma unroll
                for (int nt = 0; nt < 4; nt++)
                    mma16816(accZ[mt][nt], a[mt], v[nt >> 1][nt & 1], v[nt >> 1][(nt & 1) + 2]);
            // H: hi then lo
            ldm4(v[0], bS + G1_BHH + boff + k16 * 32);
            ldm4(v[1], bS + G1_BHH + boff + 16 * SA * 2 + k16 * 32);
            #pragma unroll
            for (int mt = 0; mt < 2; mt++)
                #pragma unroll
                for (int nt = 0; nt < 4; nt++)
                    mma16816(accH[mt][nt], a[mt], v[nt >> 1][nt & 1], v[nt >> 1][(nt & 1) + 2]);
            ldm4(v[0], bS + G1_BHL + boff + k16 * 32);
            ldm4(v[1], bS + G1_BHL + boff + 16 * SA * 2 + k16 * 32);
            #pragma unroll
            for (int mt = 0; mt < 2; mt++)
                #pragma unroll
                for (int nt = 0; nt < 4; nt++)
                    mma16816(accH[mt][nt], a[mt], v[nt >> 1][nt & 1], v[nt >> 1][(nt & 1) + 2]);
        }
        __syncthreads();
        if (it + 2 < 16) g1_load(it + 2, st, m0, n0, tid, s);
        CP_COMMIT();
    }

    // epilogue: a = 1 - sigmoid(z), b = sigmoid(z) * h -> interleaved g_ab
    #pragma unroll
    for (int mt = 0; mt < 2; mt++) {
        const int row = m0 + wm * 32 + mt * 16 + (l >> 2);
        #pragma unroll
        for (int nt = 0; nt < 4; nt++) {
            const int col = n0 + wn * 32 + nt * 8 + (l & 3) * 2;
            const float bz0 = __ldg(bz + col), bz1 = __ldg(bz + col + 1);
            const float bh0 = __ldg(bh + col), bh1 = __ldg(bh + col + 1);
            float z[4] = {accZ[mt][nt][0] + bz0, accZ[mt][nt][1] + bz1,
                          accZ[mt][nt][2] + bz0, accZ[mt][nt][3] + bz1};
            float h[4] = {accH[mt][nt][0] + bh0, accH[mt][nt][1] + bh1,
                          accH[mt][nt][2] + bh0, accH[mt][nt][3] + bh1};
            float sg[4];
            #pragma unroll
            for (int q = 0; q < 4; q++) sg[q] = 1.f / (1.f + __expf(-z[q]));
            float4 v0 = {1.f - sg[0], sg[0] * h[0], 1.f - sg[1], sg[1] * h[1]};
            float4 v1 = {1.f - sg[2], sg[2] * h[2], 1.f - sg[3], sg[3] * h[3]};
            *(float4*)(g_ab + (size_t)row * HID + col) = v0;
            *(float4*)(g_ab + (size_t)(row + 8) * HID + col) = v1;
        }
    }
}

// ---------------------------------------------------------------------------
// GEMM2: out = S Woh^T + S Wol^T + bo. Single K pass.
// smem/stage: A 10240 + Bh 5120 + Bl 5120 = 20480B; 2 stages static (40960B).
// ---------------------------------------------------------------------------
#define G2_STG 20480
#define G2_BH 10240
#define G2_BL 15360

__device__ __forceinline__ void g2_load(int chunk, int st, int m0, int n0, int tid,
                                        uint32_t s) {
    const int k0 = chunk << 5;
    const uint32_t base = s + st * G2_STG;
    #pragma unroll
    for (int j = 0; j < 2; j++) {
        const int ch = tid + j * 256, row = ch >> 2, c = ch & 3;
        cp16(base + (row * SA + c * 8) * 2,
             g_sh + (size_t)(m0 + row) * HID + k0 + c * 8);
    }
    const int row = tid >> 2, c = tid & 3;
    const uint32_t off = (row * SA + c * 8) * 2;
    const size_t gsrc = (size_t)(n0 + row) * HID + k0 + c * 8;
    cp16(base + G2_BH + off, g_woh + gsrc);
    cp16(base + G2_BL + off, g_wol + gsrc);
}

__global__ __launch_bounds__(256) void gemm2_kernel(const float* __restrict__ bo,
                                                    float* __restrict__ out) {
    __shared__ __half S2[2 * G2_STG / 2];
    const int tid = threadIdx.x, wid = tid >> 5, l = tid & 31;
    const int wm = wid & 3, wn = wid >> 2;
    const int m0 = blockIdx.y * 128, n0 = blockIdx.x * 64;

    const uint32_t s = smem_u32(S2);
    const uint32_t aoff = ((wm * 32 + (l & 15)) * SA + (l >> 4) * 8) * 2;
    const uint32_t boff = ((wn * 32 + (l & 15)) * SA + (l >> 4) * 8) * 2;

    float acc[2][4][4] = {};

    g2_load(0, 0, m0, n0, tid, s); CP_COMMIT();
    g2_load(1, 1, m0, n0, tid, s); CP_COMMIT();

    #pragma unroll 1
    for (int it = 0; it < 16; it++) {
        const int st = it & 1;
        CP_WAIT1();
        __syncthreads();
        const uint32_t bS = s + st * G2_STG;
        #pragma unroll
        for (int k16 = 0; k16 < 2; k16++) {
            uint32_t a[2][4], v[2][4];
            ldm4(a[0], bS + aoff + k16 * 32);
            ldm4(a[1], bS + aoff + 16 * SA * 2 + k16 * 32);
            ldm4(v[0], bS + G2_BH + boff + k16 * 32);
            ldm4(v[1], bS + G2_BH + boff + 16 * SA * 2 + k16 * 32);
            #pragma unroll
            for (int mt = 0; mt < 2; mt++)
                #pragma unroll
                for (int nt = 0; nt < 4; nt++)
                    mma16816(acc[mt][nt], a[mt], v[nt >> 1][nt & 1], v[nt >> 1][(nt & 1) + 2]);
            ldm4(v[0], bS + G2_BL + boff + k16 * 32);
            ldm4(v[1], bS + G2_BL + boff + 16 * SA * 2 + k16 * 32);
            #pragma unroll
            for (int mt = 0; mt < 2; mt++)
                #pragma unroll
                for (int nt = 0; nt < 4; nt++)
                    mma16816(acc[mt][nt], a[mt], v[nt >> 1][nt & 1], v[nt >> 1][(nt & 1) + 2]);
        }
        __syncthreads();
        if (it + 2 < 16) g2_load(it + 2, st, m0, n0, tid, s);
        CP_COMMIT();
    }

    #pragma unroll
    for (int mt = 0; mt < 2; mt++) {
        const int row = m0 + wm * 32 + mt * 16 + (l >> 2);
        #pragma unroll
        for (int nt = 0; nt < 4; nt++) {
            const int col = n0 + wn * 32 + nt * 8 + (l & 3) * 2;
            const float b0 = __ldg(bo + col), b1 = __ldg(bo + col + 1);
            *(float2*)(out + (size_t)row * HID + col) =
                make_float2(acc[mt][nt][0] + b0, acc[mt][nt][1] + b1);
            *(float2*)(out + (size_t)(row + 8) * HID + col) =
                make_float2(acc[mt][nt][2] + b0, acc[mt][nt][3] + b1);
        }
    }
}

// ---------------------------------------------------------------------------
// Scan phases: s_t = a_t * s_{t-1} + b_t.  2 channels/thread, float4 loads.
// ---------------------------------------------------------------------------
__global__ __launch_bounds__(256) void scan_phase1() {
    const int c = blockIdx.x, t = threadIdx.x;
    const float4* p = (const float4*)(g_ab + (size_t)c * CHUNK_L * HID) + t;
    float A0 = 1.f, B0 = 0.f, A1 = 1.f, B1 = 0.f;
    #pragma unroll 8
    for (int i = 0; i < CHUNK_L; i++) {
        float4 v = p[(size_t)i * 256];
        A0 = v.x * A0; B0 = v.x * B0 + v.y;
        A1 = v.z * A1; B1 = v.z * B1 + v.w;
    }
    *(float4*)(g_agg + c * HID + 2 * t) = make_float4(A0, B0, A1, B1);
}

__global__ __launch_bounds__(512) void scan_phase2() {
    const int h = threadIdx.x;
    float s = 0.f;
    #pragma unroll 8
    for (int c = 0; c < NCHUNK; c++) {
        g_pref[c * HID + h] = s;
        float2 ag = g_agg[c * HID + h];
        s = ag.x * s + ag.y;
    }
}

__global__ __launch_bounds__(256) void scan_phase3() {
    const int c = blockIdx.x, t = threadIdx.x;
    const float4* p = (const float4*)(g_ab + (size_t)c * CHUNK_L * HID) + t;
    __half2* q = (__half2*)(g_sh + (size_t)c * CHUNK_L * HID) + t;
    float s0 = g_pref[c * HID + 2 * t];
    float s1 = g_pref[c * HID + 2 * t + 1];
    #pragma unroll 8
    for (int i = 0; i < CHUNK_L; i++) {
        float4 v = p[(size_t)i * 256];
        s0 = v.x * s0 + v.y;
        s1 = v.z * s1 + v.w;
        q[(size_t)i * 256] = __halves2half2(__float2half(s0), __float2half(s1));
    }
}

// ---------------------------------------------------------------------------
extern "C" void kernel_launch(void* const* d_in, const int* in_sizes, int n_in,
                              void* d_out, int out_size) {
    const float* xs = (const float*)d_in[0];
    const float* Wz = (const float*)d_in[1];
    const float* bz = (const float*)d_in[2];
    const float* Wh = (const float*)d_in[3];
    const float* bh = (const float*)d_in[4];
    const float* Wo = (const float*)d_in[5];
    const float* bo = (const float*)d_in[6];
    float* out = (float*)d_out;

    __half *xh, *wzh, *wzl, *whh, *whl, *woh, *wol;
    cudaGetSymbolAddress((void**)&xh, g_xh);
    cudaGetSymbolAddress((void**)&wzh, g_wzh);
    cudaGetSymbolAddress((void**)&wzl, g_wzl);
    cudaGetSymbolAddress((void**)&whh, g_whh);
    cudaGetSymbolAddress((void**)&whl, g_whl);
    cudaGetSymbolAddress((void**)&woh, g_woh);
    cudaGetSymbolAddress((void**)&wol, g_wol);

    cudaFuncSetAttribute(gemm1_kernel, cudaFuncAttributeMaxDynamicSharedMemorySize,
                         2 * G1_STG);

    const int nX2 = T_LEN * HID / 2, nW2 = HID * HID / 2;
    convert_hi<<<(nX2 + 255) / 256, 256>>>(xs, xh, nX2);
    convert_split<<<(nW2 + 255) / 256, 256>>>(Wz, wzh, wzl, nW2);
    convert_split<<<(nW2 + 255) / 256, 256>>>(Wh, whh, whl, nW2);
    convert_split<<<(nW2 + 255) / 256, 256>>>(Wo, woh, wol, nW2);

    gemm1_kernel<<<dim3(HID / 64, T_LEN / 128), 256, 2 * G1_STG>>>(bz, bh);

    scan_phase1<<<NCHUNK, 256>>>();
    scan_phase2<<<1, 512>>>();
    scan_phase3<<<NCHUNK, 256>>>();

    gemm2_kernel<<<dim3(HID / 64, T_LEN / 128), 256>>>(bo, out);
}

// round 6
// speedup vs baseline: 5.5846x; 1.2631x over previous
#include <cuda_runtime.h>
#include <cuda_fp16.h>
#include <cstdint>

#define T_LEN 16384
#define HID   512
#define NCHUNK 256
#define CHUNK_L 64
#define SA 40          // smem row stride in halves (32 used + 8 pad)

// ---------------------------------------------------------------------------
// Device scratch (no runtime allocation allowed)
// ---------------------------------------------------------------------------
__device__ __half g_xh[T_LEN * HID];
__device__ __half g_wz[HID * HID], g_wh[HID * HID], g_wo[HID * HID];
__device__ float2 g_ab[T_LEN * HID];      // (a, b) interleaved
__device__ __half g_sh[T_LEN * HID];
__device__ float2 g_agg[NCHUNK * HID];    // (A, B) per chunk
__device__ float g_pref[NCHUNK * HID];

// ---------------------------------------------------------------------------
// PTX helpers (sm_80-era: valid under compute_103 virtual arch)
// ---------------------------------------------------------------------------
__device__ __forceinline__ uint32_t smem_u32(const void* p) {
    uint32_t a;
    asm("{ .reg .u64 t; cvta.to.shared.u64 t, %1; cvt.u32.u64 %0, t; }" : "=r"(a) : "l"(p));
    return a;
}

__device__ __forceinline__ void cp16(uint32_t dst, const void* src) {
    asm volatile("cp.async.ca.shared.global [%0], [%1], 16;" :: "r"(dst), "l"(src));
}
#define CP_COMMIT() asm volatile("cp.async.commit_group;" ::: "memory")
#define CP_WAIT1()  asm volatile("cp.async.wait_group 1;" ::: "memory")

__device__ __forceinline__ void ldm4(uint32_t* r, uint32_t addr) {
    asm volatile("ldmatrix.sync.aligned.m8n8.x4.shared.b16 {%0,%1,%2,%3}, [%4];"
                 : "=r"(r[0]), "=r"(r[1]), "=r"(r[2]), "=r"(r[3]) : "r"(addr));
}

__device__ __forceinline__ void mma16816(float* d, const uint32_t* a, uint32_t b0, uint32_t b1) {
    asm volatile(
        "mma.sync.aligned.m16n8k16.row.col.f32.f16.f16.f32 "
        "{%0,%1,%2,%3}, {%4,%5,%6,%7}, {%8,%9}, {%0,%1,%2,%3};"
        : "+f"(d[0]), "+f"(d[1]), "+f"(d[2]), "+f"(d[3])
        : "r"(a[0]), "r"(a[1]), "r"(a[2]), "r"(a[3]), "r"(b0), "r"(b1));
}

// ---------------------------------------------------------------------------
// Fused fp32 -> fp16 converter: X then Wz, Wh, Wo (hi only), one launch.
// ---------------------------------------------------------------------------
#define NX2 (T_LEN * HID / 2)
#define NW2 (HID * HID / 2)

__global__ __launch_bounds__(256) void convert_all(const float* __restrict__ xs,
                                                   const float* __restrict__ Wz,
                                                   const float* __restrict__ Wh,
                                                   const float* __restrict__ Wo) {
    int i = blockIdx.x * 256 + threadIdx.x;
    const float* src;
    __half* dst;
    int j;
    if (i < NX2)                 { src = xs; dst = g_xh; j = i; }
    else if (i < NX2 + NW2)      { src = Wz; dst = g_wz; j = i - NX2; }
    else if (i < NX2 + 2 * NW2)  { src = Wh; dst = g_wh; j = i - NX2 - NW2; }
    else if (i < NX2 + 3 * NW2)  { src = Wo; dst = g_wo; j = i - NX2 - 2 * NW2; }
    else return;
    float2 x = *(const float2*)(src + j * 2);
    *(__half2*)(dst + j * 2) = __halves2half2(__float2half(x.x), __float2half(x.y));
}

// ---------------------------------------------------------------------------
// GEMM1: Z = X Wz^T + bz, Hc = X Wh^T + bh -> g_ab = (1-sig(Z), sig(Z)*Hc)
// Single fp16 product. BM=128 BN=64 BK=32, 16 chunks, 2-stage cp.async.
// smem/stage: A 10240 + Bz 5120 + Bh 5120 = 20480B (2 stages static = 40KB).
// ---------------------------------------------------------------------------
#define G1_STG 20480
#define G1_BZ 10240
#define G1_BH 15360

__device__ __forceinline__ void g1_load(int chunk, int st, int m0, int n0, int tid,
                                        uint32_t s) {
    const int k0 = chunk << 5;
    const uint32_t base = s + st * G1_STG;
    #pragma unroll
    for (int j = 0; j < 2; j++) {
        const int ch = tid + j * 256, row = ch >> 2, c = ch & 3;
        cp16(base + (row * SA + c * 8) * 2,
             g_xh + (size_t)(m0 + row) * HID + k0 + c * 8);
    }
    const int row = tid >> 2, c = tid & 3;
    const uint32_t off = (row * SA + c * 8) * 2;
    const size_t gsrc = (size_t)(n0 + row) * HID + k0 + c * 8;
    cp16(base + G1_BZ + off, g_wz + gsrc);
    cp16(base + G1_BH + off, g_wh + gsrc);
}

__global__ __launch_bounds__(256) void gemm1_kernel(const float* __restrict__ bz,
                                                    const float* __restrict__ bh) {
    __shared__ __half S1[2 * G1_STG / 2];
    const int tid = threadIdx.x, wid = tid >> 5, l = tid & 31;
    const int wm = wid & 3, wn = wid >> 2;
    const int m0 = blockIdx.y * 128, n0 = blockIdx.x * 64;

    const uint32_t s = smem_u32(S1);
    const uint32_t aoff = ((wm * 32 + (l & 15)) * SA + (l >> 4) * 8) * 2;
    const uint32_t boff = ((wn * 32 + (l & 15)) * SA + (l >> 4) * 8) * 2;

    float accZ[2][4][4] = {}, accH[2][4][4] = {};

    g1_load(0, 0, m0, n0, tid, s); CP_COMMIT();
    g1_load(1, 1, m0, n0, tid, s); CP_COMMIT();

    #pragma unroll 1
    for (int it = 0; it < 16; it++) {
        const int st = it & 1;
        CP_WAIT1();
        __syncthreads();
        const uint32_t bS = s + st * G1_STG;
        #pragma unroll
        for (int k16 = 0; k16 < 2; k16++) {
            uint32_t a[2][4], vz[2][4], vh[2][4];
            ldm4(a[0], bS + aoff + k16 * 32);
            ldm4(a[1], bS + aoff + 16 * SA * 2 + k16 * 32);
            ldm4(vz[0], bS + G1_BZ + boff + k16 * 32);
            ldm4(vz[1], bS + G1_BZ + boff + 16 * SA * 2 + k16 * 32);
            ldm4(vh[0], bS + G1_BH + boff + k16 * 32);
            ldm4(vh[1], bS + G1_BH + boff + 16 * SA * 2 + k16 * 32);
            #pragma unroll
            for (int mt = 0; mt < 2; mt++)
                #pragma unroll
                for (int nt = 0; nt < 4; nt++) {
                    const int p = nt >> 1, q = nt & 1;
                    mma16816(accZ[mt][nt], a[mt], vz[p][q], vz[p][q + 2]);
                    mma16816(accH[mt][nt], a[mt], vh[p][q], vh[p][q + 2]);
                }
        }
        __syncthreads();
        if (it + 2 < 16) g1_load(it + 2, st, m0, n0, tid, s);
        CP_COMMIT();
    }

    // epilogue: a = 1 - sigmoid(z), b = sigmoid(z) * h -> interleaved g_ab
    #pragma unroll
    for (int mt = 0; mt < 2; mt++) {
        const int row = m0 + wm * 32 + mt * 16 + (l >> 2);
        #pragma unroll
        for (int nt = 0; nt < 4; nt++) {
            const int col = n0 + wn * 32 + nt * 8 + (l & 3) * 2;
            const float bz0 = __ldg(bz + col), bz1 = __ldg(bz + col + 1);
            const float bh0 = __ldg(bh + col), bh1 = __ldg(bh + col + 1);
            float z[4] = {accZ[mt][nt][0] + bz0, accZ[mt][nt][1] + bz1,
                          accZ[mt][nt][2] + bz0, accZ[mt][nt][3] + bz1};
            float h[4] = {accH[mt][nt][0] + bh0, accH[mt][nt][1] + bh1,
                          accH[mt][nt][2] + bh0, accH[mt][nt][3] + bh1};
            float sg[4];
            #pragma unroll
            for (int q = 0; q < 4; q++) sg[q] = 1.f / (1.f + __expf(-z[q]));
            float4 v0 = {1.f - sg[0], sg[0] * h[0], 1.f - sg[1], sg[1] * h[1]};
            float4 v1 = {1.f - sg[2], sg[2] * h[2], 1.f - sg[3], sg[3] * h[3]};
            *(float4*)(g_ab + (size_t)row * HID + col) = v0;
            *(float4*)(g_ab + (size_t)(row + 8) * HID + col) = v1;
        }
    }
}

// ---------------------------------------------------------------------------
// GEMM2: out = S Wo^T + bo. Single fp16 product.
// smem/stage: A 10240 + B 5120 = 15360B (2 stages = 30KB static).
// ---------------------------------------------------------------------------
#define G2_STG 15360
#define G2_B 10240

__device__ __forceinline__ void g2_load(int chunk, int st, int m0, int n0, int tid,
                                        uint32_t s) {
    const int k0 = chunk << 5;
    const uint32_t base = s + st * G2_STG;
    #pragma unroll
    for (int j = 0; j < 2; j++) {
        const int ch = tid + j * 256, row = ch >> 2, c = ch & 3;
        cp16(base + (row * SA + c * 8) * 2,
             g_sh + (size_t)(m0 + row) * HID + k0 + c * 8);
    }
    const int row = tid >> 2, c = tid & 3;
    cp16(base + G2_B + (row * SA + c * 8) * 2,
         g_wo + (size_t)(n0 + row) * HID + k0 + c * 8);
}

__global__ __launch_bounds__(256) void gemm2_kernel(const float* __restrict__ bo,
                                                    float* __restrict__ out) {
    __shared__ __half S2[2 * G2_STG / 2];
    const int tid = threadIdx.x, wid = tid >> 5, l = tid & 31;
    const int wm = wid & 3, wn = wid >> 2;
    const int m0 = blockIdx.y * 128, n0 = blockIdx.x * 64;

    const uint32_t s = smem_u32(S2);
    const uint32_t aoff = ((wm * 32 + (l & 15)) * SA + (l >> 4) * 8) * 2;
    const uint32_t boff = ((wn * 32 + (l & 15)) * SA + (l >> 4) * 8) * 2;

    float acc[2][4][4] = {};

    g2_load(0, 0, m0, n0, tid, s); CP_COMMIT();
    g2_load(1, 1, m0, n0, tid, s); CP_COMMIT();

    #pragma unroll 1
    for (int it = 0; it < 16; it++) {
        const int st = it & 1;
        CP_WAIT1();
        __syncthreads();
        const uint32_t bS = s + st * G2_STG;
        #pragma unroll
        for (int k16 = 0; k16 < 2; k16++) {
            uint32_t a[2][4], v[2][4];
            ldm4(a[0], bS + aoff + k16 * 32);
            ldm4(a[1], bS + aoff + 16 * SA * 2 + k16 * 32);
            ldm4(v[0], bS + G2_B + boff + k16 * 32);
            ldm4(v[1], bS + G2_B + boff + 16 * SA * 2 + k16 * 32);
            #pragma unroll
            for (int mt = 0; mt < 2; mt++)
                #pragma unroll
                for (int nt = 0; nt < 4; nt++)
                    mma16816(acc[mt][nt], a[mt], v[nt >> 1][nt & 1], v[nt >> 1][(nt & 1) + 2]);
        }
        __syncthreads();
        if (it + 2 < 16) g2_load(it + 2, st, m0, n0, tid, s);
        CP_COMMIT();
    }

    #pragma unroll
    for (int mt = 0; mt < 2; mt++) {
        const int row = m0 + wm * 32 + mt * 16 + (l >> 2);
        #pragma unroll
        for (int nt = 0; nt < 4; nt++) {
            const int col = n0 + wn * 32 + nt * 8 + (l & 3) * 2;
            const float b0 = __ldg(bo + col), b1 = __ldg(bo + col + 1);
            *(float2*)(out + (size_t)row * HID + col) =
                make_float2(acc[mt][nt][0] + b0, acc[mt][nt][1] + b1);
            *(float2*)(out + (size_t)(row + 8) * HID + col) =
                make_float2(acc[mt][nt][2] + b0, acc[mt][nt][3] + b1);
        }
    }
}

// ---------------------------------------------------------------------------
// Scan phases: s_t = a_t * s_{t-1} + b_t.  2 channels/thread, float4 loads.
// ---------------------------------------------------------------------------
__global__ __launch_bounds__(256) void scan_phase1() {
    const int c = blockIdx.x, t = threadIdx.x;
    const float4* p = (const float4*)(g_ab + (size_t)c * CHUNK_L * HID) + t;
    float A0 = 1.f, B0 = 0.f, A1 = 1.f, B1 = 0.f;
    #pragma unroll 8
    for (int i = 0; i < CHUNK_L; i++) {
        float4 v = p[(size_t)i * 256];
        A0 = v.x * A0; B0 = v.x * B0 + v.y;
        A1 = v.z * A1; B1 = v.z * B1 + v.w;
    }
    *(float4*)(g_agg + c * HID + 2 * t) = make_float4(A0, B0, A1, B1);
}

__global__ __launch_bounds__(512) void scan_phase2() {
    const int h = threadIdx.x;
    float s = 0.f;
    #pragma unroll 8
    for (int c = 0; c < NCHUNK; c++) {
        g_pref[c * HID + h] = s;
        float2 ag = g_agg[c * HID + h];
        s = ag.x * s + ag.y;
    }
}

__global__ __launch_bounds__(256) void scan_phase3() {
    const int c = blockIdx.x, t = threadIdx.x;
    const float4* p = (const float4*)(g_ab + (size_t)c * CHUNK_L * HID) + t;
    __half2* q = (__half2*)(g_sh + (size_t)c * CHUNK_L * HID) + t;
    float s0 = g_pref[c * HID + 2 * t];
    float s1 = g_pref[c * HID + 2 * t + 1];
    #pragma unroll 8
    for (int i = 0; i < CHUNK_L; i++) {
        float4 v = p[(size_t)i * 256];
        s0 = v.x * s0 + v.y;
        s1 = v.z * s1 + v.w;
        q[(size_t)i * 256] = __halves2half2(__float2half(s0), __float2half(s1));
    }
}

// ---------------------------------------------------------------------------
extern "C" void kernel_launch(void* const* d_in, const int* in_sizes, int n_in,
                              void* d_out, int out_size) {
    const float* xs = (const float*)d_in[0];
    const float* Wz = (const float*)d_in[1];
    const float* bz = (const float*)d_in[2];
    const float* Wh = (const float*)d_in[3];
    const float* bh = (const float*)d_in[4];
    const float* Wo = (const float*)d_in[5];
    const float* bo = (const float*)d_in[6];
    float* out = (float*)d_out;

    const int ntot = NX2 + 3 * NW2;
    convert_all<<<(ntot + 255) / 256, 256>>>(xs, Wz, Wh, Wo);

    gemm1_kernel<<<dim3(HID / 64, T_LEN / 128), 256>>>(bz, bh);

    scan_phase1<<<NCHUNK, 256>>>();
    scan_phase2<<<1, 512>>>();
    scan_phase3<<<NCHUNK, 256>>>();

    gemm2_kernel<<<dim3(HID / 64, T_LEN / 128), 256>>>(bo, out);
}

// round 7
// speedup vs baseline: 7.1776x; 1.2853x over previous
#include <cuda_runtime.h>
#include <cuda_fp16.h>
#include <cstdint>

#define T_LEN 16384
#define HID   512
#define NCHUNK 256
#define CHUNK_L 64
#define SA 40          // smem row stride in halves (32 used + 8 pad)

// ---------------------------------------------------------------------------
// Device scratch (no runtime allocation allowed)
// ---------------------------------------------------------------------------
__device__ __half g_xh[T_LEN * HID];
__device__ __half g_wz[HID * HID], g_wh[HID * HID], g_wo[HID * HID];
__device__ float2 g_ab[T_LEN * HID];      // (a, b) interleaved
__device__ __half g_sh[T_LEN * HID];
__device__ float2 g_agg[NCHUNK * HID];    // (A, B) per chunk
__device__ float g_pref[NCHUNK * HID];

// ---------------------------------------------------------------------------
// PTX helpers (sm_80-era: valid under compute_103 virtual arch)
// ---------------------------------------------------------------------------
__device__ __forceinline__ uint32_t smem_u32(const void* p) {
    uint32_t a;
    asm("{ .reg .u64 t; cvta.to.shared.u64 t, %1; cvt.u32.u64 %0, t; }" : "=r"(a) : "l"(p));
    return a;
}

__device__ __forceinline__ void cp16(uint32_t dst, const void* src) {
    asm volatile("cp.async.ca.shared.global [%0], [%1], 16;" :: "r"(dst), "l"(src));
}
#define CP_COMMIT() asm volatile("cp.async.commit_group;" ::: "memory")
#define CP_WAIT1()  asm volatile("cp.async.wait_group 1;" ::: "memory")

__device__ __forceinline__ void ldm4(uint32_t* r, uint32_t addr) {
    asm volatile("ldmatrix.sync.aligned.m8n8.x4.shared.b16 {%0,%1,%2,%3}, [%4];"
                 : "=r"(r[0]), "=r"(r[1]), "=r"(r[2]), "=r"(r[3]) : "r"(addr));
}

__device__ __forceinline__ void mma16816(float* d, const uint32_t* a, uint32_t b0, uint32_t b1) {
    asm volatile(
        "mma.sync.aligned.m16n8k16.row.col.f32.f16.f16.f32 "
        "{%0,%1,%2,%3}, {%4,%5,%6,%7}, {%8,%9}, {%0,%1,%2,%3};"
        : "+f"(d[0]), "+f"(d[1]), "+f"(d[2]), "+f"(d[3])
        : "r"(a[0]), "r"(a[1]), "r"(a[2]), "r"(a[3]), "r"(b0), "r"(b1));
}

// ---------------------------------------------------------------------------
// Fused fp32 -> fp16 converter: X then Wz, Wh, Wo, one launch.
// ---------------------------------------------------------------------------
#define NX2 (T_LEN * HID / 2)
#define NW2 (HID * HID / 2)

__global__ __launch_bounds__(256) void convert_all(const float* __restrict__ xs,
                                                   const float* __restrict__ Wz,
                                                   const float* __restrict__ Wh,
                                                   const float* __restrict__ Wo) {
    int i = blockIdx.x * 256 + threadIdx.x;
    const float* src;
    __half* dst;
    int j;
    if (i < NX2)                 { src = xs; dst = g_xh; j = i; }
    else if (i < NX2 + NW2)      { src = Wz; dst = g_wz; j = i - NX2; }
    else if (i < NX2 + 2 * NW2)  { src = Wh; dst = g_wh; j = i - NX2 - NW2; }
    else if (i < NX2 + 3 * NW2)  { src = Wo; dst = g_wo; j = i - NX2 - 2 * NW2; }
    else return;
    float2 x = *(const float2*)(src + j * 2);
    *(__half2*)(dst + j * 2) = __halves2half2(__float2half(x.x), __float2half(x.y));
}

// ---------------------------------------------------------------------------
// GEMM1: Z = X Wz^T + bz, Hc = X Wh^T + bh -> g_ab = (1-sig(Z), sig(Z)*Hc)
// BM=128 BN=64 BK=32, 16 chunks, 2-stage cp.async.
// ---------------------------------------------------------------------------
#define G1_STG 20480
#define G1_BZ 10240
#define G1_BH 15360

__device__ __forceinline__ void g1_load(int chunk, int st, int m0, int n0, int tid,
                                        uint32_t s) {
    const int k0 = chunk << 5;
    const uint32_t base = s + st * G1_STG;
    #pragma unroll
    for (int j = 0; j < 2; j++) {
        const int ch = tid + j * 256, row = ch >> 2, c = ch & 3;
        cp16(base + (row * SA + c * 8) * 2,
             g_xh + (size_t)(m0 + row) * HID + k0 + c * 8);
    }
    const int row = tid >> 2, c = tid & 3;
    const uint32_t off = (row * SA + c * 8) * 2;
    const size_t gsrc = (size_t)(n0 + row) * HID + k0 + c * 8;
    cp16(base + G1_BZ + off, g_wz + gsrc);
    cp16(base + G1_BH + off, g_wh + gsrc);
}

__global__ __launch_bounds__(256) void gemm1_kernel(const float* __restrict__ bz,
                                                    const float* __restrict__ bh) {
    __shared__ __half S1[2 * G1_STG / 2];
    const int tid = threadIdx.x, wid = tid >> 5, l = tid & 31;
    const int wm = wid & 3, wn = wid >> 2;
    const int m0 = blockIdx.y * 128, n0 = blockIdx.x * 64;

    const uint32_t s = smem_u32(S1);
    const uint32_t aoff = ((wm * 32 + (l & 15)) * SA + (l >> 4) * 8) * 2;
    const uint32_t boff = ((wn * 32 + (l & 15)) * SA + (l >> 4) * 8) * 2;

    float accZ[2][4][4] = {}, accH[2][4][4] = {};

    g1_load(0, 0, m0, n0, tid, s); CP_COMMIT();
    g1_load(1, 1, m0, n0, tid, s); CP_COMMIT();

    #pragma unroll 1
    for (int it = 0; it < 16; it++) {
        const int st = it & 1;
        CP_WAIT1();
        __syncthreads();
        const uint32_t bS = s + st * G1_STG;
        #pragma unroll
        for (int k16 = 0; k16 < 2; k16++) {
            uint32_t a[2][4], vz[2][4], vh[2][4];
            ldm4(a[0], bS + aoff + k16 * 32);
            ldm4(a[1], bS + aoff + 16 * SA * 2 + k16 * 32);
            ldm4(vz[0], bS + G1_BZ + boff + k16 * 32);
            ldm4(vz[1], bS + G1_BZ + boff + 16 * SA * 2 + k16 * 32);
            ldm4(vh[0], bS + G1_BH + boff + k16 * 32);
            ldm4(vh[1], bS + G1_BH + boff + 16 * SA * 2 + k16 * 32);
            #pragma unroll
            for (int mt = 0; mt < 2; mt++)
                #pragma unroll
                for (int nt = 0; nt < 4; nt++) {
                    const int p = nt >> 1, q = nt & 1;
                    mma16816(accZ[mt][nt], a[mt], vz[p][q], vz[p][q + 2]);
                    mma16816(accH[mt][nt], a[mt], vh[p][q], vh[p][q + 2]);
                }
        }
        __syncthreads();
        if (it + 2 < 16) g1_load(it + 2, st, m0, n0, tid, s);
        CP_COMMIT();
    }

    #pragma unroll
    for (int mt = 0; mt < 2; mt++) {
        const int row = m0 + wm * 32 + mt * 16 + (l >> 2);
        #pragma unroll
        for (int nt = 0; nt < 4; nt++) {
            const int col = n0 + wn * 32 + nt * 8 + (l & 3) * 2;
            const float bz0 = __ldg(bz + col), bz1 = __ldg(bz + col + 1);
            const float bh0 = __ldg(bh + col), bh1 = __ldg(bh + col + 1);
            float z[4] = {accZ[mt][nt][0] + bz0, accZ[mt][nt][1] + bz1,
                          accZ[mt][nt][2] + bz0, accZ[mt][nt][3] + bz1};
            float h[4] = {accH[mt][nt][0] + bh0, accH[mt][nt][1] + bh1,
                          accH[mt][nt][2] + bh0, accH[mt][nt][3] + bh1};
            float sg[4];
            #pragma unroll
            for (int q = 0; q < 4; q++) sg[q] = 1.f / (1.f + __expf(-z[q]));
            float4 v0 = {1.f - sg[0], sg[0] * h[0], 1.f - sg[1], sg[1] * h[1]};
            float4 v1 = {1.f - sg[2], sg[2] * h[2], 1.f - sg[3], sg[3] * h[3]};
            *(float4*)(g_ab + (size_t)row * HID + col) = v0;
            *(float4*)(g_ab + (size_t)(row + 8) * HID + col) = v1;
        }
    }
}

// ---------------------------------------------------------------------------
// GEMM2: out = S Wo^T + bo.
// ---------------------------------------------------------------------------
#define G2_STG 15360
#define G2_B 10240

__device__ __forceinline__ void g2_load(int chunk, int st, int m0, int n0, int tid,
                                        uint32_t s) {
    const int k0 = chunk << 5;
    const uint32_t base = s + st * G2_STG;
    #pragma unroll
    for (int j = 0; j < 2; j++) {
        const int ch = tid + j * 256, row = ch >> 2, c = ch & 3;
        cp16(base + (row * SA + c * 8) * 2,
             g_sh + (size_t)(m0 + row) * HID + k0 + c * 8);
    }
    const int row = tid >> 2, c = tid & 3;
    cp16(base + G2_B + (row * SA + c * 8) * 2,
         g_wo + (size_t)(n0 + row) * HID + k0 + c * 8);
}

__global__ __launch_bounds__(256) void gemm2_kernel(const float* __restrict__ bo,
                                                    float* __restrict__ out) {
    __shared__ __half S2[2 * G2_STG / 2];
    const int tid = threadIdx.x, wid = tid >> 5, l = tid & 31;
    const int wm = wid & 3, wn = wid >> 2;
    const int m0 = blockIdx.y * 128, n0 = blockIdx.x * 64;

    const uint32_t s = smem_u32(S2);
    const uint32_t aoff = ((wm * 32 + (l & 15)) * SA + (l >> 4) * 8) * 2;
    const uint32_t boff = ((wn * 32 + (l & 15)) * SA + (l >> 4) * 8) * 2;

    float acc[2][4][4] = {};

    g2_load(0, 0, m0, n0, tid, s); CP_COMMIT();
    g2_load(1, 1, m0, n0, tid, s); CP_COMMIT();

    #pragma unroll 1
    for (int it = 0; it < 16; it++) {
        const int st = it & 1;
        CP_WAIT1();
        __syncthreads();
        const uint32_t bS = s + st * G2_STG;
        #pragma unroll
        for (int k16 = 0; k16 < 2; k16++) {
            uint32_t a[2][4], v[2][4];
            ldm4(a[0], bS + aoff + k16 * 32);
            ldm4(a[1], bS + aoff + 16 * SA * 2 + k16 * 32);
            ldm4(v[0], bS + G2_B + boff + k16 * 32);
            ldm4(v[1], bS + G2_B + boff + 16 * SA * 2 + k16 * 32);
            #pragma unroll
            for (int mt = 0; mt < 2; mt++)
                #pragma unroll
                for (int nt = 0; nt < 4; nt++)
                    mma16816(acc[mt][nt], a[mt], v[nt >> 1][nt & 1], v[nt >> 1][(nt & 1) + 2]);
        }
        __syncthreads();
        if (it + 2 < 16) g2_load(it + 2, st, m0, n0, tid, s);
        CP_COMMIT();
    }

    #pragma unroll
    for (int mt = 0; mt < 2; mt++) {
        const int row = m0 + wm * 32 + mt * 16 + (l >> 2);
        #pragma unroll
        for (int nt = 0; nt < 4; nt++) {
            const int col = n0 + wn * 32 + nt * 8 + (l & 3) * 2;
            const float b0 = __ldg(bo + col), b1 = __ldg(bo + col + 1);
            *(float2*)(out + (size_t)row * HID + col) =
                make_float2(acc[mt][nt][0] + b0, acc[mt][nt][1] + b1);
            *(float2*)(out + (size_t)(row + 8) * HID + col) =
                make_float2(acc[mt][nt][2] + b0, acc[mt][nt][3] + b1);
        }
    }
}

// ---------------------------------------------------------------------------
// Scan phase 1: per-chunk aggregates. 2 channels/thread, float4 loads.
// ---------------------------------------------------------------------------
__global__ __launch_bounds__(256) void scan_phase1() {
    const int c = blockIdx.x, t = threadIdx.x;
    const float4* p = (const float4*)(g_ab + (size_t)c * CHUNK_L * HID) + t;
    float A0 = 1.f, B0 = 0.f, A1 = 1.f, B1 = 0.f;
    #pragma unroll 8
    for (int i = 0; i < CHUNK_L; i++) {
        float4 v = p[(size_t)i * 256];
        A0 = v.x * A0; B0 = v.x * B0 + v.y;
        A1 = v.z * A1; B1 = v.z * B1 + v.w;
    }
    *(float4*)(g_agg + c * HID + 2 * t) = make_float4(A0, B0, A1, B1);
}

// ---------------------------------------------------------------------------
// Scan phase 2: Kogge-Stone parallel scan over chunk aggregates.
// grid = 512 blocks (one per channel), 256 threads (one per chunk).
// compose(earlier, later): A = A_l*A_e ; B = A_l*B_e + B_l.
// Prefix state entering chunk c = B_inclusive[c-1] (s0 = 0).
// ---------------------------------------------------------------------------
__global__ __launch_bounds__(256) void scan_phase2() {
    const int h = blockIdx.x, c = threadIdx.x;
    __shared__ float sA[NCHUNK], sB[NCHUNK];
    float2 ag = g_agg[c * HID + h];
    float A = ag.x, B = ag.y;
    sA[c] = A; sB[c] = B;
    __syncthreads();
    #pragma unroll
    for (int d = 1; d < NCHUNK; d <<= 1) {
        float pA = 1.f, pB = 0.f;
        if (c >= d) { pA = sA[c - d]; pB = sB[c - d]; }
        __syncthreads();
        if (c >= d) {
            B = A * pB + B;
            A = A * pA;
            sA[c] = A; sB[c] = B;
        }
        __syncthreads();
    }
    g_pref[c * HID + h] = (c == 0) ? 0.f : sB[c - 1];
}

// ---------------------------------------------------------------------------
// Scan phase 3: apply prefixes, emit states as fp16.
// ---------------------------------------------------------------------------
__global__ __launch_bounds__(256) void scan_phase3() {
    const int c = blockIdx.x, t = threadIdx.x;
    const float4* p = (const float4*)(g_ab + (size_t)c * CHUNK_L * HID) + t;
    __half2* q = (__half2*)(g_sh + (size_t)c * CHUNK_L * HID) + t;
    float s0 = g_pref[c * HID + 2 * t];
    float s1 = g_pref[c * HID + 2 * t + 1];
    #pragma unroll 8
    for (int i = 0; i < CHUNK_L; i++) {
        float4 v = p[(size_t)i * 256];
        s0 = v.x * s0 + v.y;
        s1 = v.z * s1 + v.w;
        q[(size_t)i * 256] = __halves2half2(__float2half(s0), __float2half(s1));
    }
}

// ---------------------------------------------------------------------------
extern "C" void kernel_launch(void* const* d_in, const int* in_sizes, int n_in,
                              void* d_out, int out_size) {
    const float* xs = (const float*)d_in[0];
    const float* Wz = (const float*)d_in[1];
    const float* bz = (const float*)d_in[2];
    const float* Wh = (const float*)d_in[3];
    const float* bh = (const float*)d_in[4];
    const float* Wo = (const float*)d_in[5];
    const float* bo = (const float*)d_in[6];
    float* out = (float*)d_out;

    const int ntot = NX2 + 3 * NW2;
    convert_all<<<(ntot + 255) / 256, 256>>>(xs, Wz, Wh, Wo);

    gemm1_kernel<<<dim3(HID / 64, T_LEN / 128), 256>>>(bz, bh);

    scan_phase1<<<NCHUNK, 256>>>();
    scan_phase2<<<HID, NCHUNK>>>();
    scan_phase3<<<NCHUNK, 256>>>();

    gemm2_kernel<<<dim3(HID / 64, T_LEN / 128), 256>>>(bo, out);
}